// round 7
// baseline (speedup 1.0000x reference)
#include <cuda_runtime.h>
#include <cuda_bf16.h>
#include <cstdint>

// TemplateEncoder: out (B=2, N=1024, N=1024, 16) fp32 = 128 MiB, store-BW bound.
//
// one_hot(bin,22) @ W + b -> LN -> ReLU depends only on bin: precompute a
// 22x16 table; out_row(b,i,j) = table[bin(i,j)] * min(conf_i, conf_j).
//
// Two phases per block (1024 blocks = one wave):
//   A: compute (cp, table_byte_off) once per (i-half, j) row -> smem (2048 x float2)
//   B: hot loop = LDS.64 pair + LDS.128 table + 2x f32x2 mul + STG.128, x32.

namespace {

constexpr int   TD    = 16;
constexpr float BIN_W = 40.0f / 21.0f;
constexpr float INV_W = 21.0f / 40.0f;
constexpr int   TBL_STRIDE = 20;   // floats: 80B rows, 16B-aligned

__device__ __forceinline__ float2 mul_f32x2(float2 a, unsigned long long s) {
    unsigned long long av;
    asm("mov.b64 %0, {%1, %2};" : "=l"(av) : "f"(a.x), "f"(a.y));
    asm("mul.rn.f32x2 %0, %0, %1;" : "+l"(av) : "l"(s));
    float2 r;
    asm("mov.b64 {%0, %1}, %2;" : "=f"(r.x), "=f"(r.y) : "l"(av));
    return r;
}

__global__ __launch_bounds__(256, 8) void template_encoder_kernel(
    const float* __restrict__ coords,   // (B, N, 3)
    const float* __restrict__ conf,     // (B, N)
    const float* __restrict__ Wm,       // (22, 16)
    const float* __restrict__ bv,       // (16)
    const float* __restrict__ gam,      // (16)
    const float* __restrict__ bet,      // (16)
    float4* __restrict__ out)
{
    __shared__ float  table[22][TBL_STRIDE];
    __shared__ float2 s_pair[2048];     // (cp, byte-offset-as-int) per (half, j)

    const int tid = threadIdx.x;
    const int b   = blockIdx.x >> 9;
    const int i0  = blockIdx.x & 511;
    const int gb  = b << 10;

    // ---- 22x16 bin table: relu(LN(W[k]+b)*gamma+beta) ----
    if (tid < 22) {
        float h[TD];
        float mu = 0.0f;
        #pragma unroll
        for (int d = 0; d < TD; ++d) { h[d] = Wm[tid * TD + d] + bv[d]; mu += h[d]; }
        mu *= (1.0f / TD);
        float var = 0.0f;
        #pragma unroll
        for (int d = 0; d < TD; ++d) { float t = h[d] - mu; var = fmaf(t, t, var); }
        var *= (1.0f / TD);
        const float inv = rsqrtf(var + 1e-5f);
        #pragma unroll
        for (int d = 0; d < TD; ++d)
            table[tid][d] = fmaxf((h[d] - mu) * inv * gam[d] + bet[d], 0.0f);
    }

    // ---- Phase A: (cp, table byte-offset) for all 2048 (half, j) rows ----
    float cix[2], ciy[2], ciz[2], cfi[2];
    #pragma unroll
    for (int half = 0; half < 2; ++half) {
        const int gi = gb + i0 + (half << 9);
        cix[half] = __ldg(coords + gi * 3 + 0);
        ciy[half] = __ldg(coords + gi * 3 + 1);
        ciz[half] = __ldg(coords + gi * 3 + 2);
        cfi[half] = __ldg(conf + gi);
    }

    #pragma unroll
    for (int q = 0; q < 8; ++q) {
        const int idx  = (q << 8) + tid;       // 0..2047
        const int half = idx >> 10;
        const int j    = idx & 1023;
        const int gj   = gb + j;

        const float cjx = coords[gj * 3 + 0];
        const float cjy = coords[gj * 3 + 1];
        const float cjz = coords[gj * 3 + 2];
        const float cfj = conf[gj];

        const float dx = cix[half] - cjx;
        const float dy = ciy[half] - cjy;
        const float dz = ciz[half] - cjz;
        const float dist = sqrtf(fmaf(dx, dx, fmaf(dy, dy, fmaf(dz, dz, 1e-8f))));

        // searchsorted(edges, dist, 'left'), clip to [0,20]; exact vs f32 edges.
        int c = (int)(dist * INV_W);
        c = c > 21 ? 21 : c;
        const float fc = (float)c;
        int cnt = c;
        if (c     <= 20 &&  fc         * BIN_W < dist) ++cnt;
        if (c + 1 <= 20 && (fc + 1.0f) * BIN_W < dist) ++cnt;
        int bin = cnt > 20 ? 20 : cnt;
        if (!(cfi[half] > 0.0f && cfj > 0.0f)) bin = 21;

        float2 pr;
        pr.x = fminf(cfi[half], cfj);
        pr.y = __int_as_float(bin * (TBL_STRIDE * 4));   // byte offset of table row
        s_pair[idx] = pr;
    }
    __syncthreads();

    // ---- Phase B: 32 iterations of pure scaled-row stores ----
    const int jl    = tid >> 2;                  // row within 64-row tile
    const int part  = tid & 3;                   // float4 slice of the feature row
    const char* tbl_part =
        reinterpret_cast<const char*>(&table[0][0]) + (part << 4);
    const float2* pair_base = s_pair + jl;       // + t*64 via immediate
    float4* out_base0 = out + (((gb + i0) << 12) | tid);            // half 0
    float4* out_base1 = out + ((((gb + i0) + 512) << 12) | tid);    // half 1

    #pragma unroll
    for (int t = 0; t < 32; ++t) {
        const int   half = t >> 4;
        const int   k    = t & 15;
        const float2 pr  = pair_base[(t << 6)];  // quad-broadcast LDS.64

        float4 v = *reinterpret_cast<const float4*>(
            tbl_part + __float_as_int(pr.y));    // LDS.128 table slice

        unsigned long long s2;
        asm("mov.b64 %0, {%1, %1};" : "=l"(s2) : "r"(__float_as_uint(pr.x)));
        float2 lo = mul_f32x2(make_float2(v.x, v.y), s2);
        float2 hi = mul_f32x2(make_float2(v.z, v.w), s2);
        v.x = lo.x; v.y = lo.y; v.z = hi.x; v.w = hi.y;

        float4* dst = (half ? out_base1 : out_base0) + (k << 8);
        __stcs(dst, v);
    }
}

} // namespace

extern "C" void kernel_launch(void* const* d_in, const int* in_sizes, int n_in,
                              void* d_out, int out_size) {
    const float* coords = (const float*)d_in[0];
    const float* conf   = (const float*)d_in[1];
    const float* Wm     = (const float*)d_in[2];
    const float* bv     = (const float*)d_in[3];
    const float* gam    = (const float*)d_in[4];
    const float* bet    = (const float*)d_in[5];
    template_encoder_kernel<<<1024, 256>>>(coords, conf, Wm, bv, gam, bet,
                                           (float4*)d_out);
}